// round 4
// baseline (speedup 1.0000x reference)
#include <cuda_runtime.h>
#include <cuda_fp16.h>
#include <cstdint>

#define BB 8
#define NN 1024
#define FIN 64
#define FOUT 128
#define HH 4
#define DD 32
#define TI 32
#define LOG2E 1.4426950408889634f

// device-global scratch. Transposed + permuted h: [b][f][j_perm], hi/lo fp16 split.
// Within each 32-node group, slot s holds node j = 2*(s>>3) + ((s&7)>>1)*8 + (s&1).
__device__ __align__(16) __half g_hhT[BB * FOUT * NN];
__device__ __align__(16) __half g_hlT[BB * FOUT * NN];
__device__ float g_src[BB * NN * HH];   // pre-scaled by log2e
__device__ float g_dst[BB * NN * HH];

__device__ __forceinline__ float ex2f(float x) {
    float r;
    asm("ex2.approx.ftz.f32 %0, %1;" : "=f"(r) : "f"(x));
    return r;
}
__device__ __forceinline__ void mma16816(float* d, unsigned a0, unsigned a1,
                                         unsigned a2, unsigned a3,
                                         unsigned b0, unsigned b1) {
    asm volatile(
        "mma.sync.aligned.m16n8k16.row.col.f32.f16.f16.f32 "
        "{%0,%1,%2,%3},{%4,%5,%6,%7},{%8,%9},{%0,%1,%2,%3};"
        : "+f"(d[0]), "+f"(d[1]), "+f"(d[2]), "+f"(d[3])
        : "r"(a0), "r"(a1), "r"(a2), "r"(a3), "r"(b0), "r"(b1));
}

// ---------------- Kernel 1: h = x@W -> permuted transposed hi/lo, e_src/e_dst ----------------
// one block = 32 nodes
__global__ __launch_bounds__(256) void gat_k1(
    const float* __restrict__ x, const float* __restrict__ W, const float* __restrict__ a)
{
    __shared__ float sW[FIN * FOUT];    // 32 KB
    __shared__ float sx[32 * FIN];      // 8 KB
    __shared__ float sh[32 * FOUT];     // 16 KB
    __shared__ float sa[HH * 2 * DD];   // 1 KB

    int t  = threadIdx.x;
    int b  = blockIdx.x >> 5;
    int n0 = (blockIdx.x & 31) << 5;

    const float4* W4 = (const float4*)W;
    float4* sW4 = (float4*)sW;
    #pragma unroll
    for (int k = t; k < (FIN * FOUT) / 4; k += 256) sW4[k] = W4[k];
    const float4* x4 = (const float4*)(x + ((b << 10) + n0) * FIN);
    #pragma unroll
    for (int k = t; k < (32 * FIN) / 4; k += 256) ((float4*)sx)[k] = x4[k];
    if (t < 64) ((float4*)sa)[t] = ((const float4*)a)[t];
    __syncthreads();

    // GEMM: thread = (row r, 16-col group fi)
    {
        int r  = t >> 3;
        int fi = t & 7;
        float4 acc[4];
        #pragma unroll
        for (int q = 0; q < 4; q++) acc[q] = make_float4(0.f, 0.f, 0.f, 0.f);
        const float* xr = sx + r * FIN;
        #pragma unroll
        for (int k = 0; k < FIN; k++) {
            float xv = xr[k];
            const float4* wr = (const float4*)(sW + k * FOUT + fi * 16);
            #pragma unroll
            for (int q = 0; q < 4; q++) {
                float4 wv = wr[q];
                acc[q].x = fmaf(xv, wv.x, acc[q].x);
                acc[q].y = fmaf(xv, wv.y, acc[q].y);
                acc[q].z = fmaf(xv, wv.z, acc[q].z);
                acc[q].w = fmaf(xv, wv.w, acc[q].w);
            }
        }
        #pragma unroll
        for (int q = 0; q < 4; q++)
            *(float4*)(sh + r * FOUT + fi * 16 + q * 4) = acc[q];
    }
    __syncthreads();

    // permuted transposed hi/lo store: thread = (feature f, 16-slot half hseg)
    {
        int f = t & 127, hseg = t >> 7;
        union { __half h[16]; uint4 v[2]; } uh, ul;
        #pragma unroll
        for (int s = 0; s < 16; s++) {
            int slot = hseg * 16 + s;
            int j = 2 * (slot >> 3) + (((slot & 7) >> 1) << 3) + (slot & 1);
            float v = sh[j * FOUT + f];
            __half hi = __float2half_rn(v);
            uh.h[s] = hi;
            ul.h[s] = __float2half_rn(v - __half2float(hi));
        }
        size_t gbase = (((size_t)(b << 7) + f) << 10) + n0 + hseg * 16;
        *(uint4*)(g_hhT + gbase)     = uh.v[0];
        *(uint4*)(g_hhT + gbase + 8) = uh.v[1];
        *(uint4*)(g_hlT + gbase)     = ul.v[0];
        *(uint4*)(g_hlT + gbase + 8) = ul.v[1];
    }

    // e_src / e_dst: 32 rows x 4 heads x 2 halves = 256 dots
    {
        int rr = t >> 3, rem = t & 7, h = rem >> 1, half_ = rem & 1;
        const float* hp = sh + rr * FOUT + h * DD;
        const float* ap = sa + h * (2 * DD) + half_ * DD;
        float s = 0.f;
        #pragma unroll
        for (int d = 0; d < DD; d++) s = fmaf(hp[d], ap[d], s);
        s *= LOG2E;
        int gnr = (b << 10) + n0 + rr;
        if (half_ == 0) g_src[gnr * HH + h] = s;
        else            g_dst[gnr * HH + h] = s;
    }
}

// ---------------- Kernel 2: softmax + HMMA AV + avg_attn ----------------
// smem (bytes):
//  [0,16384)        s_dst  float[1024][4]
//  [16384,40960)    s_qA   half[4 h][32 i][96]     (64 permuted j-slots + pad)
//  [40960,90112)    s_hB   half[2 ver][128 f][96]  (64 permuted j-slots + pad)
//  [90112,90624)    s_src  float[32][4]
//  [90624,91136)    s_linv float[32][4]
//  [91136,91264)    s_empty int[32]
#define RSTR 96
#define S_QA    16384
#define S_HB    40960
#define S_SRC   90112
#define S_LINV  90624
#define S_EMPTY 91136
#define SMEM2   91264

__global__ __launch_bounds__(256, 2) void gat_k2(
    const int* __restrict__ adj, const float* __restrict__ ew,
    float* __restrict__ out, float* __restrict__ avg)
{
    extern __shared__ char smem[];
    float*  s_dst   = (float*)smem;
    __half* s_qA    = (__half*)(smem + S_QA);
    __half* s_hB    = (__half*)(smem + S_HB);
    float*  s_src   = (float*)(smem + S_SRC);
    float*  s_linv  = (float*)(smem + S_LINV);
    int*    s_empty = (int*)(smem + S_EMPTY);

    int b  = blockIdx.y;
    int i0 = blockIdx.x * TI;
    int t = threadIdx.x, w = t >> 5, lane = t & 31;

    // stage dst logits + src logits
    {
        const float4* gd4 = (const float4*)(g_dst + (b << 12));
        for (int k = t; k < NN; k += 256) ((float4*)s_dst)[k] = gd4[k];
        if (t < 128) s_src[t] = g_src[((b << 10) + i0) * 4 + t];
    }
    __syncthreads();

    // ---- phase A: denominators ----
    #pragma unroll
    for (int rr = 0; rr < 4; rr++) {
        int i = w + (rr << 3);
        int gi = i0 + i;
        const int* adjrow = adj + (size_t)gi * NN;
        float s0 = s_src[i*4+0], s1 = s_src[i*4+1], s2 = s_src[i*4+2], s3 = s_src[i*4+3];
        float l0 = 0.f, l1 = 0.f, l2 = 0.f, l3 = 0.f;
        #pragma unroll 4
        for (int jj = 0; jj < 16; jj++) {
            int j = (lane << 1) + (jj << 6);
            int2 av = *(const int2*)(adjrow + j);
            if (av.x) {
                float4 d = ((float4*)s_dst)[j]; float e;
                e = s0 + d.x; e = fmaxf(e, 0.2f*e); l0 += ex2f(e);
                e = s1 + d.y; e = fmaxf(e, 0.2f*e); l1 += ex2f(e);
                e = s2 + d.z; e = fmaxf(e, 0.2f*e); l2 += ex2f(e);
                e = s3 + d.w; e = fmaxf(e, 0.2f*e); l3 += ex2f(e);
            }
            if (av.y) {
                float4 d = ((float4*)s_dst)[j + 1]; float e;
                e = s0 + d.x; e = fmaxf(e, 0.2f*e); l0 += ex2f(e);
                e = s1 + d.y; e = fmaxf(e, 0.2f*e); l1 += ex2f(e);
                e = s2 + d.z; e = fmaxf(e, 0.2f*e); l2 += ex2f(e);
                e = s3 + d.w; e = fmaxf(e, 0.2f*e); l3 += ex2f(e);
            }
        }
        #pragma unroll
        for (int off = 16; off; off >>= 1) {
            l0 += __shfl_xor_sync(0xffffffffu, l0, off);
            l1 += __shfl_xor_sync(0xffffffffu, l1, off);
            l2 += __shfl_xor_sync(0xffffffffu, l2, off);
            l3 += __shfl_xor_sync(0xffffffffu, l3, off);
        }
        if (lane == 0) {
            int emp = !(l0 > 0.f);
            s_empty[i] = emp;
            s_linv[i*4+0] = emp ? 1.f : 1.f / l0;
            s_linv[i*4+1] = emp ? 1.f : 1.f / l1;
            s_linv[i*4+2] = emp ? 1.f : 1.f / l2;
            s_linv[i*4+3] = emp ? 1.f : 1.f / l3;
        }
    }

    // ---- main loop over 16 chunks of 64 j-nodes ----
    float dA0[4] = {0,0,0,0}, dA1[4] = {0,0,0,0};   // i-tile 0
    float dB0[4] = {0,0,0,0}, dB1[4] = {0,0,0,0};   // i-tile 1
    int h  = w >> 1;
    int nh = w & 1;
    int g  = lane >> 2;
    int tq = lane & 3;
    int ncol = (h << 5) + (nh << 4);

    // q-producer slot mapping (within 64-slot chunk): lane l -> pair j=2l,2l+1
    int qgrp = lane >> 4, qk2 = lane & 15;
    int qoff = (qgrp << 5) + ((((qk2 & 3) << 2) + (qk2 >> 2)) << 1);   // halves

    for (int c = 0; c < 16; c++) {
        __syncthreads();   // prev chunk's mma reads done

        // stage h-tile into registers (latency overlaps q-compute)
        uint4 tmp[8];
        #pragma unroll
        for (int s = 0; s < 8; s++) {
            int idx = t + (s << 8);                 // 2 ver x 128 f x 8 seg
            int ver = idx >> 10, f = (idx >> 3) & 127, seg = idx & 7;
            const __half* src = (ver ? g_hlT : g_hhT)
                + (((size_t)(b << 7) + f) << 10) + (c << 6) + (seg << 3);
            tmp[s] = *(const uint4*)src;
        }

        // q-compute (fp16 into s_qA, fragment-major) + avg_attn write
        #pragma unroll
        for (int rr = 0; rr < 4; rr++) {
            int i = w + (rr << 3);
            int gi = i0 + i;
            const int*   adjrow = adj + (size_t)gi * NN;
            const float* ewrow  = ew  + (size_t)gi * NN;
            float* avgrow = avg + ((size_t)(b * NN) + gi) * NN;
            float sv[4], lv[4];
            #pragma unroll
            for (int q = 0; q < 4; q++) { sv[q] = s_src[i*4+q]; lv[q] = s_linv[i*4+q]; }
            int emp = s_empty[i];
            int jl = lane << 1;
            int j  = (c << 6) + jl;
            int2   av  = *(const int2*)(adjrow + j);
            float2 ew2 = *(const float2*)(ewrow + j);
            float4 dA = ((float4*)s_dst)[j];
            float4 dB = ((float4*)s_dst)[j + 1];
            float dAv[4] = {dA.x, dA.y, dA.z, dA.w};
            float dBv[4] = {dB.x, dB.y, dB.z, dB.w};
            float va = 0.f, vb = 0.f;
            #pragma unroll
            for (int hh = 0; hh < 4; hh++) {
                float qa = 0.f, qb = 0.f;
                if (emp) { qa = qb = (1.f / 1024.f); }
                else {
                    if (av.x) { float e = sv[hh] + dAv[hh]; e = fmaxf(e, 0.2f*e); qa = ex2f(e); }
                    if (av.y) { float e = sv[hh] + dBv[hh]; e = fmaxf(e, 0.2f*e); qb = ex2f(e); }
                }
                va = fmaf(qa, lv[hh], va);
                vb = fmaf(qb, lv[hh], vb);
                __half2 hq = __floats2half2_rn(qa * ew2.x, qb * ew2.y);
                *(__half2*)(s_qA + ((hh << 5) + i) * RSTR + qoff) = hq;
            }
            *(float2*)(avgrow + j) = make_float2(0.25f * va * ew2.x, 0.25f * vb * ew2.y);
        }

        // commit staged h-tile (layout identical to gmem, row stride RSTR)
        #pragma unroll
        for (int s = 0; s < 8; s++) {
            int idx = t + (s << 8);
            int ver = idx >> 10, f = (idx >> 3) & 127, seg = idx & 7;
            *(uint4*)(s_hB + ((ver << 7) + f) * RSTR + (seg << 3)) = tmp[s];
        }
        __syncthreads();

        // HMMA: A = q[32 i x 64 j] (head h), B = h[64 j x 16 f] hi+lo
        #pragma unroll
        for (int ktt = 0; ktt < 2; ktt++) {
            int fo = (ktt << 5) + (tq << 3);    // halves offset within row
            uint4 aT0g  = *(uint4*)(s_qA + ((h << 5) + g)      * RSTR + fo);
            uint4 aT0g8 = *(uint4*)(s_qA + ((h << 5) + g + 8)  * RSTR + fo);
            uint4 aT1g  = *(uint4*)(s_qA + ((h << 5) + 16 + g) * RSTR + fo);
            uint4 aT1g8 = *(uint4*)(s_qA + ((h << 5) + 24 - 8 + g + 8) * RSTR + fo);
            uint4 bh0 = *(uint4*)(s_hB + (ncol + g)            * RSTR + fo);
            uint4 bh1 = *(uint4*)(s_hB + (ncol + g + 8)        * RSTR + fo);
            uint4 bl0 = *(uint4*)(s_hB + (128 + ncol + g)      * RSTR + fo);
            uint4 bl1 = *(uint4*)(s_hB + (128 + ncol + g + 8)  * RSTR + fo);
            // kt = 2*ktt  (fragments .x/.y)
            mma16816(dA0, aT0g.x, aT0g8.x, aT0g.y, aT0g8.y, bh0.x, bh0.y);
            mma16816(dA1, aT0g.x, aT0g8.x, aT0g.y, aT0g8.y, bh1.x, bh1.y);
            mma16816(dA0, aT0g.x, aT0g8.x, aT0g.y, aT0g8.y, bl0.x, bl0.y);
            mma16816(dA1, aT0g.x, aT0g8.x, aT0g.y, aT0g8.y, bl1.x, bl1.y);
            mma16816(dB0, aT1g.x, aT1g8.x, aT1g.y, aT1g8.y, bh0.x, bh0.y);
            mma16816(dB1, aT1g.x, aT1g8.x, aT1g.y, aT1g8.y, bh1.x, bh1.y);
            mma16816(dB0, aT1g.x, aT1g8.x, aT1g.y, aT1g8.y, bl0.x, bl0.y);
            mma16816(dB1, aT1g.x, aT1g8.x, aT1g.y, aT1g8.y, bl1.x, bl1.y);
            // kt = 2*ktt+1  (fragments .z/.w)
            mma16816(dA0, aT0g.z, aT0g8.z, aT0g.w, aT0g8.w, bh0.z, bh0.w);
            mma16816(dA1, aT0g.z, aT0g8.z, aT0g.w, aT0g8.w, bh1.z, bh1.w);
            mma16816(dA0, aT0g.z, aT0g8.z, aT0g.w, aT0g8.w, bl0.z, bl0.w);
            mma16816(dA1, aT0g.z, aT0g8.z, aT0g.w, aT0g8.w, bl1.z, bl1.w);
            mma16816(dB0, aT1g.z, aT1g8.z, aT1g.w, aT1g8.w, bh0.z, bh0.w);
            mma16816(dB1, aT1g.z, aT1g8.z, aT1g.w, aT1g8.w, bh1.z, bh1.w);
            mma16816(dB0, aT1g.z, aT1g8.z, aT1g.w, aT1g8.w, bl0.z, bl0.w);
            mma16816(dB1, aT1g.z, aT1g8.z, aT1g.w, aT1g8.w, bl1.z, bl1.w);
        }
    }

    // ---- epilogue: normalize + store out ----
    {
        int col = ncol + (tq << 1);
        float li0 = s_linv[g * 4 + h];
        float li8 = s_linv[(g + 8) * 4 + h];
        float li16 = s_linv[(16 + g) * 4 + h];
        float li24 = s_linv[(24 + g) * 4 + h];
        size_t r0  = ((size_t)((b << 10) + i0 + g)) << 7;
        *(float2*)(out + r0 + col)              = make_float2(dA0[0]*li0,  dA0[1]*li0);
        *(float2*)(out + r0 + col + 8)          = make_float2(dA1[0]*li0,  dA1[1]*li0);
        *(float2*)(out + r0 + (8  << 7) + col)     = make_float2(dA0[2]*li8,  dA0[3]*li8);
        *(float2*)(out + r0 + (8  << 7) + col + 8) = make_float2(dA1[2]*li8,  dA1[3]*li8);
        *(float2*)(out + r0 + (16 << 7) + col)     = make_float2(dB0[0]*li16, dB0[1]*li16);
        *(float2*)(out + r0 + (16 << 7) + col + 8) = make_float2(dB1[0]*li16, dB1[1]*li16);
        *(float2*)(out + r0 + (24 << 7) + col)     = make_float2(dB0[2]*li24, dB0[3]*li24);
        *(float2*)(out + r0 + (24 << 7) + col + 8) = make_float2(dB1[2]*li24, dB1[3]*li24);
    }
}

extern "C" void kernel_launch(void* const* d_in, const int* in_sizes, int n_in,
                              void* d_out, int out_size)
{
    (void)in_sizes; (void)n_in; (void)out_size;
    const float* x   = (const float*)d_in[0];
    const int*   adj = (const int*)d_in[1];
    const float* ew  = (const float*)d_in[2];
    const float* W   = (const float*)d_in[3];
    const float* a   = (const float*)d_in[4];
    float* out = (float*)d_out;                   // [B,N,128]
    float* avg = out + (size_t)BB * NN * FOUT;    // [B,N,N]

    cudaFuncSetAttribute(gat_k2, cudaFuncAttributeMaxDynamicSharedMemorySize, SMEM2);

    gat_k1<<<BB * NN / 32, 256>>>(x, W, a);
    gat_k2<<<dim3(NN / TI, BB), 256, SMEM2>>>(adj, ew, out, avg);
}

// round 5
// speedup vs baseline: 1.2667x; 1.2667x over previous
#include <cuda_runtime.h>
#include <cuda_fp16.h>
#include <cstdint>

#define BB 8
#define NN 1024
#define FIN 64
#define FOUT 128
#define HH 4
#define DD 32
#define TI 32
#define LOG2E 1.4426950408889634f

// device-global scratch. Transposed + permuted h: [b][f][j_perm], fp16.
// Within each 32-node group, slot s holds node j = 2*(s>>3) + (((s&7)>>1)<<3) + (s&1).
__device__ __align__(16) __half g_hT[BB * FOUT * NN];
__device__ float g_src[BB * NN * HH];   // pre-scaled by log2e
__device__ float g_dst[BB * NN * HH];

__device__ __forceinline__ float ex2f(float x) {
    float r;
    asm("ex2.approx.ftz.f32 %0, %1;" : "=f"(r) : "f"(x));
    return r;
}
__device__ __forceinline__ void mma16816(float* d, unsigned a0, unsigned a1,
                                         unsigned a2, unsigned a3,
                                         unsigned b0, unsigned b1) {
    asm volatile(
        "mma.sync.aligned.m16n8k16.row.col.f32.f16.f16.f32 "
        "{%0,%1,%2,%3},{%4,%5,%6,%7},{%8,%9},{%0,%1,%2,%3};"
        : "+f"(d[0]), "+f"(d[1]), "+f"(d[2]), "+f"(d[3])
        : "r"(a0), "r"(a1), "r"(a2), "r"(a3), "r"(b0), "r"(b1));
}

// ---------------- Kernel 1: h = x@W -> permuted transposed fp16, e_src/e_dst ----------------
// block = (b, 32-node group, 64-feature half). grid = 8*32*2 = 512
__global__ __launch_bounds__(256) void gat_k1(
    const float* __restrict__ x, const float* __restrict__ W, const float* __restrict__ a)
{
    __shared__ float sW[FIN * 64];      // 16 KB (this block's 64 W columns)
    __shared__ float sx[32 * FIN];      // 8 KB
    __shared__ float sh[32 * 64];       // 8 KB
    __shared__ float sa[HH * 2 * DD];   // 1 KB

    int t     = threadIdx.x;
    int b     = blockIdx.x >> 6;
    int n0    = ((blockIdx.x >> 1) & 31) << 5;
    int fhalf = blockIdx.x & 1;

    // cooperative loads
    {
        const float4* W4 = (const float4*)W;
        #pragma unroll
        for (int s = 0; s < 4; s++) {
            int idx = t + (s << 8);           // 0..1023 = 64 rows x 16 float4
            int row = idx >> 4, c4 = idx & 15;
            ((float4*)sW)[idx] = W4[(row << 5) + (fhalf << 4) + c4];
        }
        const float4* x4 = (const float4*)(x + ((b << 10) + n0) * FIN);
        #pragma unroll
        for (int s = 0; s < 2; s++) ((float4*)sx)[t + (s << 8)] = x4[t + (s << 8)];
        if (t < 64) ((float4*)sa)[t] = ((const float4*)a)[t];
    }
    __syncthreads();

    // GEMM: thread = (row r, 8-col group fi)
    {
        int r  = t >> 3;
        int fi = t & 7;
        float4 acc0 = make_float4(0.f,0.f,0.f,0.f), acc1 = make_float4(0.f,0.f,0.f,0.f);
        const float* xr = sx + r * FIN;
        #pragma unroll
        for (int k = 0; k < FIN; k++) {
            float xv = xr[k];
            const float4* wr = (const float4*)(sW + (k << 6) + (fi << 3));
            float4 w0 = wr[0], w1 = wr[1];
            acc0.x = fmaf(xv, w0.x, acc0.x); acc0.y = fmaf(xv, w0.y, acc0.y);
            acc0.z = fmaf(xv, w0.z, acc0.z); acc0.w = fmaf(xv, w0.w, acc0.w);
            acc1.x = fmaf(xv, w1.x, acc1.x); acc1.y = fmaf(xv, w1.y, acc1.y);
            acc1.z = fmaf(xv, w1.z, acc1.z); acc1.w = fmaf(xv, w1.w, acc1.w);
        }
        *(float4*)(sh + (r << 6) + (fi << 3))     = acc0;
        *(float4*)(sh + (r << 6) + (fi << 3) + 4) = acc1;
    }
    __syncthreads();

    // permuted transposed fp16 store: thread = (f_local = t>>2, hseg = t&3)
    {
        int f_local = t >> 2, hseg = t & 3;
        union { __half h[8]; uint4 v; } u;
        #pragma unroll
        for (int k = 0; k < 8; k++) {
            int j = 2 * hseg + ((k >> 1) << 3) + (k & 1);   // slot = hseg*8+k
            u.h[k] = __float2half_rn(sh[(j << 6) + f_local]);
        }
        int f = (fhalf << 6) + f_local;
        size_t gbase = (((size_t)(b << 7) + f) << 10) + n0 + (hseg << 3);
        *(uint4*)(g_hT + gbase) = u.v;
    }

    // e_src / e_dst: 32 rows x 2 heads x 2 halves = 128 dots of 32
    if (t < 128) {
        int rr = t >> 2, rem = t & 3, hl = rem >> 1, half_ = rem & 1;
        int head = (fhalf << 1) + hl;
        const float* hp = sh + (rr << 6) + hl * DD;
        const float* ap = sa + head * (2 * DD) + half_ * DD;
        float s = 0.f;
        #pragma unroll
        for (int d = 0; d < DD; d++) s = fmaf(hp[d], ap[d], s);
        s *= LOG2E;
        int gnr = (b << 10) + n0 + rr;
        if (half_ == 0) g_src[gnr * HH + head] = s;
        else            g_dst[gnr * HH + head] = s;
    }
}

// ---------------- Kernel 2: softmax + HMMA AV + avg_attn ----------------
// smem (bytes):
//  [0,16384)        s_dst  float[1024][4]
//  [16384,40960)    s_qA   half[4 h][32 i][96]   (64 permuted j-slots + pad)
//  [40960,65536)    s_hB   half[128 f][96]       (64 permuted j-slots + pad)
//  [65536,66048)    s_src  float[32][4]
//  [66048,66560)    s_linv float[32][4]
//  [66560,66688)    s_empty int[32]
#define RSTR 96
#define S_QA    16384
#define S_HB    40960
#define S_SRC   65536
#define S_LINV  66048
#define S_EMPTY 66560
#define SMEM2   66688

__global__ __launch_bounds__(256, 3) void gat_k2(
    const int* __restrict__ adj, const float* __restrict__ ew,
    float* __restrict__ out, float* __restrict__ avg)
{
    extern __shared__ char smem[];
    float*  s_dst   = (float*)smem;
    __half* s_qA    = (__half*)(smem + S_QA);
    __half* s_hB    = (__half*)(smem + S_HB);
    float*  s_src   = (float*)(smem + S_SRC);
    float*  s_linv  = (float*)(smem + S_LINV);
    int*    s_empty = (int*)(smem + S_EMPTY);

    int b  = blockIdx.y;
    int i0 = blockIdx.x * TI;
    int t = threadIdx.x, w = t >> 5, lane = t & 31;

    // stage dst logits + src logits
    {
        const float4* gd4 = (const float4*)(g_dst + (b << 12));
        for (int k = t; k < NN; k += 256) ((float4*)s_dst)[k] = gd4[k];
        if (t < 128) s_src[t] = g_src[((b << 10) + i0) * 4 + t];
    }
    __syncthreads();

    // ---- phase A: denominators ----
    #pragma unroll
    for (int rr = 0; rr < 4; rr++) {
        int i = w + (rr << 3);
        int gi = i0 + i;
        const int* adjrow = adj + (size_t)gi * NN;
        float s0 = s_src[i*4+0], s1 = s_src[i*4+1], s2 = s_src[i*4+2], s3 = s_src[i*4+3];
        float l0 = 0.f, l1 = 0.f, l2 = 0.f, l3 = 0.f;
        #pragma unroll 4
        for (int jj = 0; jj < 16; jj++) {
            int j = (lane << 1) + (jj << 6);
            int2 av = *(const int2*)(adjrow + j);
            if (av.x) {
                float4 d = ((float4*)s_dst)[j]; float e;
                e = s0 + d.x; e = fmaxf(e, 0.2f*e); l0 += ex2f(e);
                e = s1 + d.y; e = fmaxf(e, 0.2f*e); l1 += ex2f(e);
                e = s2 + d.z; e = fmaxf(e, 0.2f*e); l2 += ex2f(e);
                e = s3 + d.w; e = fmaxf(e, 0.2f*e); l3 += ex2f(e);
            }
            if (av.y) {
                float4 d = ((float4*)s_dst)[j + 1]; float e;
                e = s0 + d.x; e = fmaxf(e, 0.2f*e); l0 += ex2f(e);
                e = s1 + d.y; e = fmaxf(e, 0.2f*e); l1 += ex2f(e);
                e = s2 + d.z; e = fmaxf(e, 0.2f*e); l2 += ex2f(e);
                e = s3 + d.w; e = fmaxf(e, 0.2f*e); l3 += ex2f(e);
            }
        }
        #pragma unroll
        for (int off = 16; off; off >>= 1) {
            l0 += __shfl_xor_sync(0xffffffffu, l0, off);
            l1 += __shfl_xor_sync(0xffffffffu, l1, off);
            l2 += __shfl_xor_sync(0xffffffffu, l2, off);
            l3 += __shfl_xor_sync(0xffffffffu, l3, off);
        }
        if (lane == 0) {
            int emp = !(l0 > 0.f);
            s_empty[i] = emp;
            s_linv[i*4+0] = emp ? 1.f : 1.f / l0;
            s_linv[i*4+1] = emp ? 1.f : 1.f / l1;
            s_linv[i*4+2] = emp ? 1.f : 1.f / l2;
            s_linv[i*4+3] = emp ? 1.f : 1.f / l3;
        }
    }

    // ---- main loop over 16 chunks of 64 j-nodes ----
    float dA0[4] = {0,0,0,0}, dA1[4] = {0,0,0,0};   // i-tile 0 (rows 0-15)
    float dB0[4] = {0,0,0,0}, dB1[4] = {0,0,0,0};   // i-tile 1 (rows 16-31)
    int h  = w >> 1;
    int nh = w & 1;
    int g  = lane >> 2;
    int tq = lane & 3;
    int ncol = (h << 5) + (nh << 4);

    // q-producer slot mapping: lane l covers nodes 2l, 2l+1 of the chunk
    int qgrp = lane >> 4, qk2 = lane & 15;
    int qoff = (qgrp << 5) + ((((qk2 & 3) << 2) + (qk2 >> 2)) << 1);   // halves

    for (int c = 0; c < 16; c++) {
        __syncthreads();   // prev chunk's mma reads done

        // stage h-tile into registers (latency overlaps q-compute)
        uint4 tmp[4];
        #pragma unroll
        for (int s = 0; s < 4; s++) {
            int idx = t + (s << 8);                 // 128 f x 8 seg
            int f = idx >> 3, seg = idx & 7;
            const __half* src = g_hT
                + (((size_t)(b << 7) + f) << 10) + (c << 6) + (seg << 3);
            tmp[s] = *(const uint4*)src;
        }

        // q-compute (fp16 into s_qA, fragment-major) + avg_attn write
        #pragma unroll
        for (int rr = 0; rr < 4; rr++) {
            int i = w + (rr << 3);
            int gi = i0 + i;
            const int*   adjrow = adj + (size_t)gi * NN;
            const float* ewrow  = ew  + (size_t)gi * NN;
            float* avgrow = avg + ((size_t)(b * NN) + gi) * NN;
            float sv[4], lv[4];
            #pragma unroll
            for (int q = 0; q < 4; q++) { sv[q] = s_src[i*4+q]; lv[q] = s_linv[i*4+q]; }
            int emp = s_empty[i];
            int jl = lane << 1;
            int j  = (c << 6) + jl;
            int2   av  = *(const int2*)(adjrow + j);
            float2 ew2 = *(const float2*)(ewrow + j);
            float4 dA = ((float4*)s_dst)[j];
            float4 dB = ((float4*)s_dst)[j + 1];
            float dAv[4] = {dA.x, dA.y, dA.z, dA.w};
            float dBv[4] = {dB.x, dB.y, dB.z, dB.w};
            float va = 0.f, vb = 0.f;
            #pragma unroll
            for (int hh = 0; hh < 4; hh++) {
                float qa = 0.f, qb = 0.f;
                if (emp) { qa = qb = (1.f / 1024.f); }
                else {
                    if (av.x) { float e = sv[hh] + dAv[hh]; e = fmaxf(e, 0.2f*e); qa = ex2f(e); }
                    if (av.y) { float e = sv[hh] + dBv[hh]; e = fmaxf(e, 0.2f*e); qb = ex2f(e); }
                }
                va = fmaf(qa, lv[hh], va);
                vb = fmaf(qb, lv[hh], vb);
                __half2 hq = __floats2half2_rn(qa * ew2.x, qb * ew2.y);
                *(__half2*)(s_qA + ((hh << 5) + i) * RSTR + qoff) = hq;
            }
            *(float2*)(avgrow + j) = make_float2(0.25f * va * ew2.x, 0.25f * vb * ew2.y);
        }

        // commit staged h-tile (layout identical to gmem, row stride RSTR)
        #pragma unroll
        for (int s = 0; s < 4; s++) {
            int idx = t + (s << 8);
            int f = idx >> 3, seg = idx & 7;
            *(uint4*)(s_hB + f * RSTR + (seg << 3)) = tmp[s];
        }
        __syncthreads();

        // HMMA: A = q[32 i x 64 j] (head h), B = h[64 j x 16 f]
        #pragma unroll
        for (int ktt = 0; ktt < 2; ktt++) {
            int fo = (ktt << 5) + (tq << 3);    // halves offset within row
            uint4 aT0g  = *(uint4*)(s_qA + ((h << 5) + g)          * RSTR + fo);
            uint4 aT0g8 = *(uint4*)(s_qA + ((h << 5) + g + 8)      * RSTR + fo);
            uint4 aT1g  = *(uint4*)(s_qA + ((h << 5) + 16 + g)     * RSTR + fo);
            uint4 aT1g8 = *(uint4*)(s_qA + ((h << 5) + 16 + g + 8) * RSTR + fo);
            uint4 bh0 = *(uint4*)(s_hB + (ncol + g)     * RSTR + fo);
            uint4 bh1 = *(uint4*)(s_hB + (ncol + g + 8) * RSTR + fo);
            // kt = 2*ktt  (.x/.y)
            mma16816(dA0, aT0g.x, aT0g8.x, aT0g.y, aT0g8.y, bh0.x, bh0.y);
            mma16816(dA1, aT0g.x, aT0g8.x, aT0g.y, aT0g8.y, bh1.x, bh1.y);
            mma16816(dB0, aT1g.x, aT1g8.x, aT1g.y, aT1g8.y, bh0.x, bh0.y);
            mma16816(dB1, aT1g.x, aT1g8.x, aT1g.y, aT1g8.y, bh1.x, bh1.y);
            // kt = 2*ktt+1  (.z/.w)
            mma16816(dA0, aT0g.z, aT0g8.z, aT0g.w, aT0g8.w, bh0.z, bh0.w);
            mma16816(dA1, aT0g.z, aT0g8.z, aT0g.w, aT0g8.w, bh1.z, bh1.w);
            mma16816(dB0, aT1g.z, aT1g8.z, aT1g.w, aT1g8.w, bh0.z, bh0.w);
            mma16816(dB1, aT1g.z, aT1g8.z, aT1g.w, aT1g8.w, bh1.z, bh1.w);
        }
    }

    // ---- epilogue: normalize + store out ----
    {
        int col = ncol + (tq << 1);
        float li0  = s_linv[g * 4 + h];
        float li8  = s_linv[(g + 8) * 4 + h];
        float li16 = s_linv[(16 + g) * 4 + h];
        float li24 = s_linv[(24 + g) * 4 + h];
        size_t r0  = ((size_t)((b << 10) + i0 + g)) << 7;
        *(float2*)(out + r0 + col)                 = make_float2(dA0[0]*li0,  dA0[1]*li0);
        *(float2*)(out + r0 + col + 8)             = make_float2(dA1[0]*li0,  dA1[1]*li0);
        *(float2*)(out + r0 + (8  << 7) + col)     = make_float2(dA0[2]*li8,  dA0[3]*li8);
        *(float2*)(out + r0 + (8  << 7) + col + 8) = make_float2(dA1[2]*li8,  dA1[3]*li8);
        *(float2*)(out + r0 + (16 << 7) + col)     = make_float2(dB0[0]*li16, dB0[1]*li16);
        *(float2*)(out + r0 + (16 << 7) + col + 8) = make_float2(dB1[0]*li16, dB1[1]*li16);
        *(float2*)(out + r0 + (24 << 7) + col)     = make_float2(dB0[2]*li24, dB0[3]*li24);
        *(float2*)(out + r0 + (24 << 7) + col + 8) = make_float2(dB1[2]*li24, dB1[3]*li24);
    }
}

extern "C" void kernel_launch(void* const* d_in, const int* in_sizes, int n_in,
                              void* d_out, int out_size)
{
    (void)in_sizes; (void)n_in; (void)out_size;
    const float* x   = (const float*)d_in[0];
    const int*   adj = (const int*)d_in[1];
    const float* ew  = (const float*)d_in[2];
    const float* W   = (const float*)d_in[3];
    const float* a   = (const float*)d_in[4];
    float* out = (float*)d_out;                   // [B,N,128]
    float* avg = out + (size_t)BB * NN * FOUT;    // [B,N,N]

    cudaFuncSetAttribute(gat_k2, cudaFuncAttributeMaxDynamicSharedMemorySize, SMEM2);

    gat_k1<<<BB * 32 * 2, 256>>>(x, W, a);
    gat_k2<<<dim3(NN / TI, BB), 256, SMEM2>>>(adj, ew, out, avg);
}